// round 12
// baseline (speedup 1.0000x reference)
#include <cuda_runtime.h>
#include <cuda_bf16.h>
#include <cstdint>

// time_embeddings: out[b, i] = sin/cos(time[b] * 10000^(-(i//2)/640))
// B = 65536, DIM = 1280, fp32 out. HBM-write-bound (~335.5 MB out,
// ~6.6 TB/s effective = ~86% of spec at the current best, 51.2us).
//
// Round-12: same latency-hiding goal as rounds 10/11 (both died at the
// broker with no harness output) but in straight-line form: every thread
// runs EXACTLY 4 iterations (B=65536, GRID=8192), so hoist all four time[]
// loads into the prologue (4 independent __ldg -> MLP=4, one exposed
// latency total) and fully unroll the 4 compute+store bodies. Generic
// fallback loop (the proven round-9 body) handles non-exact B.
// Data path unchanged: one float8 chunk per thread, Cody-Waite +
// __sincosf, st.global.cs.v8.f32, no smem, 6 blocks/SM.

#define DIM      1280
#define C8S      (DIM / 8)     // 160 float8 chunks per row
#define BLOCK    320           // 2 rows x 160 chunks per block-iteration
#define GRID     8192          // 32768 pairs / 8192 = exactly 4 per block

__device__ __forceinline__ void emit_row(
    float t, float r0, float r1, float r2, float r3,
    float* __restrict__ out, int row, int c8)
{
    const float INV2PI = 0.15915494309189535f;
    const float HI     = 6.28125f;
    const float LO     = 1.9353071795864769e-3f;

    float a0 = t * r0, a1 = t * r1, a2 = t * r2, a3 = t * r3;

    float k0 = rintf(a0 * INV2PI), k1 = rintf(a1 * INV2PI);
    float k2 = rintf(a2 * INV2PI), k3 = rintf(a3 * INV2PI);

    float x0 = fmaf(k0, -LO, fmaf(k0, -HI, a0));
    float x1 = fmaf(k1, -LO, fmaf(k1, -HI, a1));
    float x2 = fmaf(k2, -LO, fmaf(k2, -HI, a2));
    float x3 = fmaf(k3, -LO, fmaf(k3, -HI, a3));

    float s0, c0, s1, c1, s2, c2, s3, c3;
    __sincosf(x0, &s0, &c0);
    __sincosf(x1, &s1, &c1);
    __sincosf(x2, &s2, &c2);
    __sincosf(x3, &s3, &c3);

    // even col -> sin, odd col -> cos; cols 8*c8 .. 8*c8+7 of this row
    float* p = out + (size_t)row * DIM + 8 * c8;
    asm volatile(
        "st.global.cs.v8.f32 [%0], {%1, %2, %3, %4, %5, %6, %7, %8};"
        :: "l"(p),
           "f"(s0), "f"(c0), "f"(s1), "f"(c1),
           "f"(s2), "f"(c2), "f"(s3), "f"(c3)
        : "memory");
}

__global__ __launch_bounds__(BLOCK, 6)
void time_emb_kernel(const float* __restrict__ time, float* __restrict__ out, int B)
{
    const int tid = threadIdx.x;
    const int sub = tid / C8S;              // 0/1: which row of the pair
    const int c8  = tid - sub * C8S;        // 0..159: float8 chunk in the row

    // rate(p) = 10000^(-p/640) = exp2(-log2(10000)/640 * p), p = i//2
    const float C = -13.287712379549449f / 640.0f;
    const int pb = 4 * c8;
    const float r0 = exp2f(C * (float)(pb + 0));
    const float r1 = exp2f(C * (float)(pb + 1));
    const float r2 = exp2f(C * (float)(pb + 2));
    const float r3 = exp2f(C * (float)(pb + 3));

    const int stride = 2 * GRID;            // rows consumed per grid pass
    const int row0   = 2 * blockIdx.x + sub;

    if (row0 + 3 * stride < B) {
        // Fast path (exact for the bench shape): batch all 4 scalar loads
        // so their latencies overlap (MLP=4), then 4 straight-line bodies.
        const float t0 = __ldg(&time[row0]);
        const float t1 = __ldg(&time[row0 + stride]);
        const float t2 = __ldg(&time[row0 + 2 * stride]);
        const float t3 = __ldg(&time[row0 + 3 * stride]);

        emit_row(t0, r0, r1, r2, r3, out, row0,              c8);
        emit_row(t1, r0, r1, r2, r3, out, row0 + stride,     c8);
        emit_row(t2, r0, r1, r2, r3, out, row0 + 2 * stride, c8);
        emit_row(t3, r0, r1, r2, r3, out, row0 + 3 * stride, c8);

        // Any rows beyond the 4th pass (only if B > 4*stride)
        for (int row = row0 + 4 * stride; row < B; row += stride)
            emit_row(__ldg(&time[row]), r0, r1, r2, r3, out, row, c8);
    } else {
        // Generic fallback (non-exact B): proven round-9 loop.
        for (int row = row0; row < B; row += stride)
            emit_row(__ldg(&time[row]), r0, r1, r2, r3, out, row, c8);
    }
}

extern "C" void kernel_launch(void* const* d_in, const int* in_sizes, int n_in,
                              void* d_out, int out_size)
{
    const float* time = (const float*)d_in[0];
    float* out = (float*)d_out;
    const int B = in_sizes[0];

    time_emb_kernel<<<GRID, BLOCK>>>(time, out, B);
}

// round 14
// speedup vs baseline: 1.0050x; 1.0050x over previous
#include <cuda_runtime.h>
#include <cuda_bf16.h>
#include <cstdint>

// time_embeddings: out[b, i] = sin/cos(time[b] * 10000^(-(i//2)/640))
// B = 65536, DIM = 1280, fp32 out. HBM-write-bound: 335.5 MB written.
//
// FINAL (round-9 winner; round-13 resubmit died to a broker infra flake on
// a byte-identical, previously-passing binary — conclusively not kernel
// content). 51.2us timed = ~6.55 TB/s effective write bandwidth (~86% of
// spec). Converged — measured and rejected: TMA bulk stores (slower),
// one-wave persistent (skew-serialized), 128b stores (slower),
// finer/coarser grain (convex, min here), load prefetch/MLP batching
// (neutral; latency already covered by 60 warps/SM multithreading).
//
// Design:
//  - BLOCK=320: thread <-> one float8 chunk; block emits a full ROW PAIR
//    (2 x 5120 B contiguous) per iteration -> perfect coalescing.
//  - GRID=8192: 32768 row-pairs / 8192 blocks = exactly 4 iterations per
//    block, uniform work, ~9 scheduling waves of 6-blocks/SM residency.
//  - rates exp2f'd once per thread, reused across 4 rows.
//  - Cody-Waite reduction (2pi = 6.28125 + LO; k<=160 exact for t<1000)
//    + __sincosf on |x|<=pi: rel_err 7.2e-6, ~8 MUFU per 8 outputs.
//  - st.global.cs.v8.f32: 256-bit streaming stores, evict-first.
//  - 32 regs, no smem, no barriers.

#define DIM      1280
#define C8S      (DIM / 8)     // 160 float8 chunks per row
#define BLOCK    320           // 2 rows x 160 chunks per block-iteration
#define GRID     8192          // 32768 pairs / 8192 = exactly 4 per block

__global__ __launch_bounds__(BLOCK, 6)
void time_emb_kernel(const float* __restrict__ time, float* __restrict__ out, int B)
{
    const int tid = threadIdx.x;
    const int sub = tid / C8S;              // 0/1: which row of the pair
    const int c8  = tid - sub * C8S;        // 0..159: float8 chunk in the row

    // rate(p) = 10000^(-p/640) = exp2(-log2(10000)/640 * p), p = i//2
    const float C = -13.287712379549449f / 640.0f;
    const int pb = 4 * c8;                  // first pair index of this chunk
    const float r0 = exp2f(C * (float)(pb + 0));
    const float r1 = exp2f(C * (float)(pb + 1));
    const float r2 = exp2f(C * (float)(pb + 2));
    const float r3 = exp2f(C * (float)(pb + 3));

    // Cody-Waite: 2*pi = HI + LO, HI=6.28125 exact for k<=160 (angle<=1000)
    const float INV2PI = 0.15915494309189535f;
    const float HI     = 6.28125f;
    const float LO     = 1.9353071795864769e-3f;

    const int stride = 2 * GRID;            // rows consumed per grid pass
    for (int row = 2 * blockIdx.x + sub; row < B; row += stride) {
        const float t = __ldg(&time[row]);

        float a0 = t * r0, a1 = t * r1, a2 = t * r2, a3 = t * r3;

        float k0 = rintf(a0 * INV2PI), k1 = rintf(a1 * INV2PI);
        float k2 = rintf(a2 * INV2PI), k3 = rintf(a3 * INV2PI);

        float x0 = fmaf(k0, -LO, fmaf(k0, -HI, a0));
        float x1 = fmaf(k1, -LO, fmaf(k1, -HI, a1));
        float x2 = fmaf(k2, -LO, fmaf(k2, -HI, a2));
        float x3 = fmaf(k3, -LO, fmaf(k3, -HI, a3));

        float s0, c0, s1, c1, s2, c2, s3, c3;
        __sincosf(x0, &s0, &c0);
        __sincosf(x1, &s1, &c1);
        __sincosf(x2, &s2, &c2);
        __sincosf(x3, &s3, &c3);

        // even col -> sin, odd col -> cos; cols 8*c8 .. 8*c8+7 of this row
        float* p = out + (size_t)row * DIM + 8 * c8;
        asm volatile(
            "st.global.cs.v8.f32 [%0], {%1, %2, %3, %4, %5, %6, %7, %8};"
            :: "l"(p),
               "f"(s0), "f"(c0), "f"(s1), "f"(c1),
               "f"(s2), "f"(c2), "f"(s3), "f"(c3)
            : "memory");
    }
}

extern "C" void kernel_launch(void* const* d_in, const int* in_sizes, int n_in,
                              void* d_out, int out_size)
{
    const float* time = (const float*)d_in[0];
    float* out = (float*)d_out;
    const int B = in_sizes[0];

    time_emb_kernel<<<GRID, BLOCK>>>(time, out, B);
}

// round 15
// speedup vs baseline: 1.0069x; 1.0019x over previous
#include <cuda_runtime.h>
#include <cuda_bf16.h>
#include <cstdint>

// time_embeddings: out[b, i] = sin/cos(time[b] * 10000^(-(i//2)/640))
// B = 65536, DIM = 1280, fp32 out. HBM-write-bound: 335.5 MB written,
// best so far 51.2us (~6.55 TB/s effective, ~86% of spec).
//
// Round-15: occupancy probe. BLOCK=320 capped residency at 60/64 warps/SM.
// Row-purity of warps only needs 160 chunks/row % 32 == 0 (true), not
// 320-thread blocks. BLOCK=256 / GRID=10240 gives 8 blocks/SM = 64 warps
// (+6.7% latency hiding). Grid stride 10240*256 = 160*16384 is an exact
// multiple of 160, so each thread's chunk (c8 = g % 160) is INVARIANT
// across its exactly-4 iterations -> rates still exp2f'd once; row simply
// advances by 16384/iteration. Data path unchanged from the round-9
// winner: Cody-Waite + __sincosf, st.global.cs.v8.f32, no smem.

#define DIM      1280
#define C8S      (DIM / 8)     // 160 float8 chunks per row
#define BLOCK    256
#define GRID     10240         // 10240*256 threads = 160*16384 chunk slots
#define ROWSTEP  16384         // rows advanced per iteration
#define NITER    4             // 65536 / 16384

__global__ __launch_bounds__(BLOCK, 8)
void time_emb_kernel(const float* __restrict__ time, float* __restrict__ out, int B)
{
    const int g   = blockIdx.x * BLOCK + threadIdx.x;   // flat chunk-slot id
    const int c8  = g % C8S;                            // fixed chunk 0..159
    const int row0 = g / C8S;                           // base row 0..16383

    // rate(p) = 10000^(-p/640) = exp2(-log2(10000)/640 * p), p = i//2
    const float C = -13.287712379549449f / 640.0f;
    const int pb = 4 * c8;                  // first pair index of this chunk
    const float r0 = exp2f(C * (float)(pb + 0));
    const float r1 = exp2f(C * (float)(pb + 1));
    const float r2 = exp2f(C * (float)(pb + 2));
    const float r3 = exp2f(C * (float)(pb + 3));

    // Cody-Waite: 2*pi = HI + LO, HI=6.28125 exact for k<=160 (angle<=1000)
    const float INV2PI = 0.15915494309189535f;
    const float HI     = 6.28125f;
    const float LO     = 1.9353071795864769e-3f;

    for (int row = row0; row < B; row += ROWSTEP) {
        const float t = __ldg(&time[row]);   // warp-uniform (warp is row-pure)

        float a0 = t * r0, a1 = t * r1, a2 = t * r2, a3 = t * r3;

        float k0 = rintf(a0 * INV2PI), k1 = rintf(a1 * INV2PI);
        float k2 = rintf(a2 * INV2PI), k3 = rintf(a3 * INV2PI);

        float x0 = fmaf(k0, -LO, fmaf(k0, -HI, a0));
        float x1 = fmaf(k1, -LO, fmaf(k1, -HI, a1));
        float x2 = fmaf(k2, -LO, fmaf(k2, -HI, a2));
        float x3 = fmaf(k3, -LO, fmaf(k3, -HI, a3));

        float s0, c0, s1, c1, s2, c2, s3, c3;
        __sincosf(x0, &s0, &c0);
        __sincosf(x1, &s1, &c1);
        __sincosf(x2, &s2, &c2);
        __sincosf(x3, &s3, &c3);

        // even col -> sin, odd col -> cos; cols 8*c8 .. 8*c8+7 of this row
        float* p = out + (size_t)row * DIM + 8 * c8;
        asm volatile(
            "st.global.cs.v8.f32 [%0], {%1, %2, %3, %4, %5, %6, %7, %8};"
            :: "l"(p),
               "f"(s0), "f"(c0), "f"(s1), "f"(c1),
               "f"(s2), "f"(c2), "f"(s3), "f"(c3)
            : "memory");
    }
}

extern "C" void kernel_launch(void* const* d_in, const int* in_sizes, int n_in,
                              void* d_out, int out_size)
{
    const float* time = (const float*)d_in[0];
    float* out = (float*)d_out;
    const int B = in_sizes[0];

    time_emb_kernel<<<GRID, BLOCK>>>(time, out, B);
}